// round 5
// baseline (speedup 1.0000x reference)
#include <cuda_runtime.h>
#include <cuda_bf16.h>
#include <mma.h>
#include <cstdint>

using namespace nvcuda;

#define NN 100000
#define NE 1600000
#define DD 128
#define KK 256   // concat K: [agg*inv | h]

// ---------------- static device scratch (no allocations allowed) ----------------
__device__ float g_agg[(size_t)NN * DD];   // scatter-sum accumulator
__device__ float g_buf0[(size_t)NN * DD];  // layer-1 output
__device__ float g_buf1[(size_t)NN * DD];  // layer-2 output
__device__ float g_inv[NN];                // degree count, then 1/max(cnt,1)
// pre-split concat weights per layer: [3][256][128], bf16 hi/lo
__device__ __nv_bfloat16 g_Whi[3 * KK * DD];
__device__ __nv_bfloat16 g_Wlo[3 * KK * DD];

// ---------------- utility kernels ----------------
__global__ void zero_agg_kernel() {
    size_t stride = (size_t)gridDim.x * blockDim.x;
    size_t n4 = (size_t)NN * DD / 4;
    float4 z = make_float4(0.f, 0.f, 0.f, 0.f);
    for (size_t v = (size_t)blockIdx.x * blockDim.x + threadIdx.x; v < n4; v += stride)
        reinterpret_cast<float4*>(g_agg)[v] = z;
}

__global__ void zero_inv_kernel() {
    int i = blockIdx.x * blockDim.x + threadIdx.x;
    if (i < NN) g_inv[i] = 0.f;
}

__global__ void count_kernel(const int* __restrict__ dst) {
    int stride = gridDim.x * blockDim.x;
    for (int e = blockIdx.x * blockDim.x + threadIdx.x; e < NE; e += stride)
        atomicAdd(&g_inv[dst[e]], 1.0f);
}

__global__ void invert_kernel() {
    int i = blockIdx.x * blockDim.x + threadIdx.x;
    if (i < NN) g_inv[i] = 1.0f / fmaxf(g_inv[i], 1.0f);
}

// split concat weight [Wl;Wr] per layer into bf16 hi/lo
__global__ void convert_w_kernel(const float* __restrict__ Wl,
                                 const float* __restrict__ Wr) {
    int idx = blockIdx.x * blockDim.x + threadIdx.x;
    if (idx >= 3 * KK * DD) return;
    int l = idx / (KK * DD);
    int r = idx - l * (KK * DD);
    int k = r / DD;
    int n = r - k * DD;
    float v = (k < DD) ? Wl[(size_t)l * DD * DD + k * DD + n]
                       : Wr[(size_t)l * DD * DD + (k - DD) * DD + n];
    __nv_bfloat16 hi = __float2bfloat16_rn(v);
    float res = v - __bfloat162float(hi);
    g_Whi[idx] = hi;
    g_Wlo[idx] = __float2bfloat16_rn(res);
}

// ---------------- scatter: one warp per edge, float4 atomicAdd intrinsic ------
__global__ void scatter_kernel(const float* __restrict__ xin,
                               const int* __restrict__ src,
                               const int* __restrict__ dst,
                               int hsel) {
    const float* __restrict__ x =
        (hsel == 0) ? xin : (hsel == 1) ? (const float*)g_buf0 : (const float*)g_buf1;
    int gw   = (blockIdx.x * blockDim.x + threadIdx.x) >> 5;
    int lane = threadIdx.x & 31;
    int nw   = (gridDim.x * blockDim.x) >> 5;
    for (int e = gw; e < NE; e += nw) {
        int s = __ldg(src + e);
        int d = __ldg(dst + e);
        float4 v = *reinterpret_cast<const float4*>(x + (size_t)s * DD + lane * 4);
        float4* p = reinterpret_cast<float4*>(g_agg + (size_t)d * DD + lane * 4);
        atomicAdd(p, v);
    }
}

// -------- split helper: float4 -> 4x(hi,lo) bf16 stored to smem --------
__device__ __forceinline__ void split_store4(__nv_bfloat16* ph, __nv_bfloat16* pl,
                                             float4 v) {
    __nv_bfloat16 hx = __float2bfloat16_rn(v.x);
    __nv_bfloat16 hy = __float2bfloat16_rn(v.y);
    __nv_bfloat16 hz = __float2bfloat16_rn(v.z);
    __nv_bfloat16 hw = __float2bfloat16_rn(v.w);
    __nv_bfloat162 h01; h01.x = hx; h01.y = hy;
    __nv_bfloat162 h23; h23.x = hz; h23.y = hw;
    *reinterpret_cast<__nv_bfloat162*>(ph)     = h01;
    *reinterpret_cast<__nv_bfloat162*>(ph + 2) = h23;
    __nv_bfloat162 l01;
    l01.x = __float2bfloat16_rn(v.x - __bfloat162float(hx));
    l01.y = __float2bfloat16_rn(v.y - __bfloat162float(hy));
    __nv_bfloat162 l23;
    l23.x = __float2bfloat16_rn(v.z - __bfloat162float(hz));
    l23.y = __float2bfloat16_rn(v.w - __bfloat162float(hw));
    *reinterpret_cast<__nv_bfloat162*>(pl)     = l01;
    *reinterpret_cast<__nv_bfloat162*>(pl + 2) = l23;
}

// ---------------- tensor-core GEMM via wmma (bf16 3-MMA split) ----------------
// Block tile: 128 rows x 64 cols, K=256 in steps of 16.
// 8 warps as 4(m) x 2(n); warp tile 32x32 = 2x2 wmma 16x16x16 fragments.
// out = (agg*inv)@Wl + h@Wr + bias + h (+relu)
#define STAGE_LD 68
#define SMEM_BYTES (128 * STAGE_LD * 4)   // 34816: stage aliases the tiles

__global__ __launch_bounds__(256, 2)
void sage_wmma_kernel(const float* __restrict__ xin,
                      float* __restrict__ oout,
                      const float* __restrict__ bias,
                      int lw,            // weight base offset = layer*KK*DD
                      int hsel, int osel, int do_relu) {
    const float* __restrict__ h =
        (hsel == 0) ? xin : (hsel == 1) ? (const float*)g_buf0 : (const float*)g_buf1;
    float* __restrict__ out =
        (osel == 0) ? (float*)g_buf0 : (osel == 1) ? (float*)g_buf1 : oout;

    __shared__ __align__(16) char smem_raw[SMEM_BYTES];
    __nv_bfloat16* Ahi = reinterpret_cast<__nv_bfloat16*>(smem_raw);          // [128][16]
    __nv_bfloat16* Alo = reinterpret_cast<__nv_bfloat16*>(smem_raw + 4096);   // [128][16]
    __nv_bfloat16* Bhi = reinterpret_cast<__nv_bfloat16*>(smem_raw + 8192);   // [16][64]
    __nv_bfloat16* Blo = reinterpret_cast<__nv_bfloat16*>(smem_raw + 10240);  // [16][64]
    float* stage = reinterpret_cast<float*>(smem_raw);                        // [128][68]

    const int tid = threadIdx.x;
    const int w  = tid >> 5;
    const int wm = w >> 1;          // 0..3  (m group of 32 rows)
    const int wn = w & 1;           // 0..1  (n group of 32 cols)
    const int rowBase = blockIdx.x * 128;
    const int nb = blockIdx.y * 64;

    // A-load coords: 2 rows per thread, float4 of K each
    const int r0 = tid >> 2;            // 0..63
    const int r1 = r0 + 64;             // 64..127
    const int kq = (tid & 3) * 4;       // 0,4,8,12
    const int arow0 = rowBase + r0;
    const int arow1 = rowBase + r1;
    const bool av0 = arow0 < NN;
    const bool av1 = arow1 < NN;
    const float inv0 = av0 ? g_inv[arow0] : 0.f;
    const float inv1 = av1 ? g_inv[arow1] : 0.f;

    // B-load coords: 16 threads per k-row, 4 bf16 each
    const int kr = tid >> 4;            // 0..15
    const int nc = (tid & 15) * 4;      // 0..60
    const __nv_bfloat16* WH = g_Whi + lw;
    const __nv_bfloat16* WL = g_Wlo + lw;

    wmma::fragment<wmma::accumulator, 16, 16, 16, float> acc[2][2];
    #pragma unroll
    for (int i = 0; i < 2; i++)
        #pragma unroll
        for (int j = 0; j < 2; j++) wmma::fill_fragment(acc[i][j], 0.f);

    for (int kb = 0; kb < KK; kb += 16) {
        // ---- A tile: 128 rows x 16 k, split to bf16 hi/lo ----
        float4 a0 = make_float4(0.f, 0.f, 0.f, 0.f);
        float4 a1 = make_float4(0.f, 0.f, 0.f, 0.f);
        if (kb < DD) {
            int k = kb + kq;
            if (av0) {
                a0 = *reinterpret_cast<const float4*>(g_agg + (size_t)arow0 * DD + k);
                a0.x *= inv0; a0.y *= inv0; a0.z *= inv0; a0.w *= inv0;
            }
            if (av1) {
                a1 = *reinterpret_cast<const float4*>(g_agg + (size_t)arow1 * DD + k);
                a1.x *= inv1; a1.y *= inv1; a1.z *= inv1; a1.w *= inv1;
            }
        } else {
            int k = kb - DD + kq;
            if (av0) a0 = *reinterpret_cast<const float4*>(h + (size_t)arow0 * DD + k);
            if (av1) a1 = *reinterpret_cast<const float4*>(h + (size_t)arow1 * DD + k);
        }
        split_store4(Ahi + r0 * 16 + kq, Alo + r0 * 16 + kq, a0);
        split_store4(Ahi + r1 * 16 + kq, Alo + r1 * 16 + kq, a1);

        // ---- B tile: 16 k x 64 n, already bf16 hi/lo in gmem ----
        {
            size_t goff = (size_t)(kb + kr) * DD + nb + nc;
            *reinterpret_cast<uint2*>(Bhi + kr * 64 + nc) =
                *reinterpret_cast<const uint2*>(WH + goff);
            *reinterpret_cast<uint2*>(Blo + kr * 64 + nc) =
                *reinterpret_cast<const uint2*>(WL + goff);
        }
        __syncthreads();

        // ---- fragments + 3-term MMA ----
        wmma::fragment<wmma::matrix_a, 16, 16, 16, __nv_bfloat16, wmma::row_major> ah[2], al[2];
        wmma::fragment<wmma::matrix_b, 16, 16, 16, __nv_bfloat16, wmma::row_major> bh[2], bl[2];
        #pragma unroll
        for (int i = 0; i < 2; i++) {
            wmma::load_matrix_sync(ah[i], Ahi + (wm * 32 + i * 16) * 16, 16);
            wmma::load_matrix_sync(al[i], Alo + (wm * 32 + i * 16) * 16, 16);
        }
        #pragma unroll
        for (int j = 0; j < 2; j++) {
            wmma::load_matrix_sync(bh[j], Bhi + wn * 32 + j * 16, 64);
            wmma::load_matrix_sync(bl[j], Blo + wn * 32 + j * 16, 64);
        }
        #pragma unroll
        for (int i = 0; i < 2; i++)
            #pragma unroll
            for (int j = 0; j < 2; j++) {
                wmma::mma_sync(acc[i][j], ah[i], bh[j], acc[i][j]);
                wmma::mma_sync(acc[i][j], ah[i], bl[j], acc[i][j]);
                wmma::mma_sync(acc[i][j], al[i], bh[j], acc[i][j]);
            }
        __syncthreads();
    }

    // ---- stage accumulators to smem ----
    #pragma unroll
    for (int i = 0; i < 2; i++)
        #pragma unroll
        for (int j = 0; j < 2; j++)
            wmma::store_matrix_sync(stage + (wm * 32 + i * 16) * STAGE_LD + wn * 32 + j * 16,
                                    acc[i][j], STAGE_LD, wmma::mem_row_major);
    __syncthreads();

    // ---- epilogue: + bias + residual (+relu), coalesced float4 ----
    #pragma unroll
    for (int it = 0; it < 8; it++) {
        int idx = it * 256 + tid;          // 0..2047
        int row = idx >> 4;                // 0..127
        int c4  = (idx & 15) * 4;          // 0..60
        int grow = rowBase + row;
        if (grow < NN) {
            const float* sp = stage + row * STAGE_LD + c4;
            float4 v  = make_float4(sp[0], sp[1], sp[2], sp[3]);
            float4 bb = *reinterpret_cast<const float4*>(bias + nb + c4);
            float4 hv = *reinterpret_cast<const float4*>(h + (size_t)grow * DD + nb + c4);
            float4 o;
            o.x = v.x + bb.x + hv.x;
            o.y = v.y + bb.y + hv.y;
            o.z = v.z + bb.z + hv.z;
            o.w = v.w + bb.w + hv.w;
            if (do_relu) {
                o.x = fmaxf(o.x, 0.f); o.y = fmaxf(o.y, 0.f);
                o.z = fmaxf(o.z, 0.f); o.w = fmaxf(o.w, 0.f);
            }
            *reinterpret_cast<float4*>(out + (size_t)grow * DD + nb + c4) = o;
        }
    }
}

// ---------------- launch ----------------
extern "C" void kernel_launch(void* const* d_in, const int* in_sizes, int n_in,
                              void* d_out, int out_size) {
    const float* x  = (const float*)d_in[0];
    const int*   ei = (const int*)d_in[1];
    const float* Wl = (const float*)d_in[2];
    const float* bl = (const float*)d_in[3];
    const float* Wr = (const float*)d_in[4];
    const int* src = ei;
    const int* dst = ei + NE;
    float* out = (float*)d_out;

    const int SB = 1184;                   // 148 SMs * 8 blocks
    dim3 GG((NN + 127) / 128, 2);          // 782 x 2 gemm blocks

    // once per launch: degree->inv, weight split
    zero_inv_kernel<<<(NN + 255) / 256, 256>>>();
    count_kernel<<<SB, 256>>>(dst);
    invert_kernel<<<(NN + 255) / 256, 256>>>();
    convert_w_kernel<<<(3 * KK * DD + 255) / 256, 256>>>(Wl, Wr);

    // layer 0: x -> g_buf0 (relu)
    zero_agg_kernel<<<SB, 256>>>();
    scatter_kernel<<<SB, 256>>>(x, src, dst, 0);
    sage_wmma_kernel<<<GG, 256>>>(x, out, bl, 0 * KK * DD, 0, 0, 1);

    // layer 1: g_buf0 -> g_buf1 (relu)
    zero_agg_kernel<<<SB, 256>>>();
    scatter_kernel<<<SB, 256>>>(x, src, dst, 1);
    sage_wmma_kernel<<<GG, 256>>>(x, out, bl + DD, 1 * KK * DD, 1, 1, 1);

    // layer 2: g_buf1 -> out (no relu)
    zero_agg_kernel<<<SB, 256>>>();
    scatter_kernel<<<SB, 256>>>(x, src, dst, 2);
    sage_wmma_kernel<<<GG, 256>>>(x, out, bl + 2 * DD, 2 * KK * DD, 2, 2, 0);
}

// round 8
// speedup vs baseline: 1.7266x; 1.7266x over previous
#include <cuda_runtime.h>
#include <cuda_bf16.h>
#include <mma.h>
#include <cstdint>

using namespace nvcuda;

#define NN 100000
#define NE 1600000
#define DD 128
#define KK 256   // concat K: [mean | h]

// ---------------- static device scratch (~167MB, within proven envelope) --------
__device__ float g_mean[(size_t)NN * DD];   // f32 mean aggregate
__device__ float g_buf0[(size_t)NN * DD];   // layer-1 output
__device__ float g_buf1[(size_t)NN * DD];   // layer-2 output
__device__ __nv_bfloat16 g_Whi[3 * KK * DD];  // concat weights hi
__device__ __nv_bfloat16 g_Wlo[3 * KK * DD];  // concat weights lo
// CSR
__device__ int g_cnt[NN];
__device__ int g_rowptr[NN + 1];
__device__ int g_cursor[NN];
__device__ int g_csrc[NE];

// ---------------- CSR build ----------------
__global__ void zero_cnt_kernel() {
    int i = blockIdx.x * blockDim.x + threadIdx.x;
    if (i < NN) g_cnt[i] = 0;
}

__global__ void hist_kernel(const int* __restrict__ dst) {
    int stride = gridDim.x * blockDim.x;
    for (int e = blockIdx.x * blockDim.x + threadIdx.x; e < NE; e += stride)
        atomicAdd(&g_cnt[dst[e]], 1);
}

// single block, 1024 threads: exclusive scan of g_cnt -> g_rowptr, copy to cursor
__global__ void scan_kernel() {
    __shared__ int sh[1024];
    const int t = threadIdx.x;
    const int chunk = (NN + 1023) / 1024;   // 98
    int start = t * chunk;
    int end   = min(start + chunk, NN);
    int s = 0;
    for (int j = start; j < end; j++) { g_rowptr[j] = s; s += g_cnt[j]; }
    sh[t] = s;
    __syncthreads();
    for (int off = 1; off < 1024; off <<= 1) {
        int v = (t >= off) ? sh[t - off] : 0;
        __syncthreads();
        sh[t] += v;
        __syncthreads();
    }
    int excl = (t == 0) ? 0 : sh[t - 1];
    for (int j = start; j < end; j++) {
        int v = g_rowptr[j] + excl;
        g_rowptr[j] = v;
        g_cursor[j] = v;
    }
    if (t == 0) g_rowptr[NN] = NE;
}

__global__ void fill_kernel(const int* __restrict__ src, const int* __restrict__ dst) {
    int stride = gridDim.x * blockDim.x;
    for (int e = blockIdx.x * blockDim.x + threadIdx.x; e < NE; e += stride) {
        int p = atomicAdd(&g_cursor[dst[e]], 1);
        g_csrc[p] = src[e];
    }
}

// ---------------- weight conversion (hi/lo bf16 split, once per launch) --------
__global__ void convert_w_kernel(const float* __restrict__ Wl,
                                 const float* __restrict__ Wr) {
    int idx = blockIdx.x * blockDim.x + threadIdx.x;
    if (idx >= 3 * KK * DD) return;
    int l = idx / (KK * DD);
    int r = idx - l * (KK * DD);
    int k = r / DD;
    int n = r - k * DD;
    float v = (k < DD) ? Wl[(size_t)l * DD * DD + k * DD + n]
                       : Wr[(size_t)l * DD * DD + (k - DD) * DD + n];
    __nv_bfloat16 hi = __float2bfloat16_rn(v);
    g_Whi[idx] = hi;
    g_Wlo[idx] = __float2bfloat16_rn(v - __bfloat162float(hi));
}

// split a float4 into packed bf16x2 hi / lo words
__device__ __forceinline__ void split4(const float4 v, uint2* ph, uint2* pl) {
    __nv_bfloat162 h01, h23, l01, l23;
    h01.x = __float2bfloat16_rn(v.x); h01.y = __float2bfloat16_rn(v.y);
    h23.x = __float2bfloat16_rn(v.z); h23.y = __float2bfloat16_rn(v.w);
    l01.x = __float2bfloat16_rn(v.x - __bfloat162float(h01.x));
    l01.y = __float2bfloat16_rn(v.y - __bfloat162float(h01.y));
    l23.x = __float2bfloat16_rn(v.z - __bfloat162float(h23.x));
    l23.y = __float2bfloat16_rn(v.w - __bfloat162float(h23.y));
    uint2 h, l;
    h.x = *reinterpret_cast<unsigned*>(&h01); h.y = *reinterpret_cast<unsigned*>(&h23);
    l.x = *reinterpret_cast<unsigned*>(&l01); l.y = *reinterpret_cast<unsigned*>(&l23);
    *ph = h; *pl = l;
}

// ---------------- gather: one warp per node (CSR), writes f32 mean -------------
__global__ void gather_kernel(const float* __restrict__ xin, int hsel) {
    const float* __restrict__ x =
        (hsel == 0) ? xin : (hsel == 1) ? (const float*)g_buf0 : (const float*)g_buf1;
    int n = (blockIdx.x * blockDim.x + threadIdx.x) >> 5;
    if (n >= NN) return;
    int lane = threadIdx.x & 31;
    int beg = g_rowptr[n];
    int end = g_rowptr[n + 1];
    float4 a = make_float4(0.f, 0.f, 0.f, 0.f);
    for (int e = beg; e < end; e++) {
        int s = __ldg(&g_csrc[e]);
        float4 v = *reinterpret_cast<const float4*>(x + (size_t)s * DD + lane * 4);
        a.x += v.x; a.y += v.y; a.z += v.z; a.w += v.w;
    }
    float invd = 1.f / fmaxf((float)(end - beg), 1.f);
    a.x *= invd; a.y *= invd; a.z *= invd; a.w *= invd;
    *reinterpret_cast<float4*>(g_mean + (size_t)n * DD + lane * 4) = a;
}

// ---------------- tensor-core GEMM (bf16 3-MMA split, on-the-fly A split) ------
// Block 128x128, K=256, BK=32. 8 warps as 2(m)x4(n); warp tile 64x32.
#define ALD 40
#define BLD 136
#define SM_AHI 0
#define SM_ALO (128 * ALD * 2)                 // 10240
#define SM_BHI (SM_ALO + 128 * ALD * 2)        // 20480
#define SM_BLO (SM_BHI + 32 * BLD * 2)         // 29184
#define SM_TOT (SM_BLO + 32 * BLD * 2)         // 37888
#define STG_LD 132

__global__ __launch_bounds__(256, 2)
void sage_wmma_kernel(const float* __restrict__ xin,
                      float* __restrict__ oout,
                      const float* __restrict__ bias,
                      int lw, int hsel, int osel, int do_relu) {
    const float* __restrict__ h =
        (hsel == 0) ? xin : (hsel == 1) ? (const float*)g_buf0 : (const float*)g_buf1;
    float* __restrict__ out =
        (osel == 0) ? (float*)g_buf0 : (osel == 1) ? (float*)g_buf1 : oout;

    __shared__ __align__(16) char smem[SM_TOT];
    __nv_bfloat16* Ahi = reinterpret_cast<__nv_bfloat16*>(smem + SM_AHI);
    __nv_bfloat16* Alo = reinterpret_cast<__nv_bfloat16*>(smem + SM_ALO);
    __nv_bfloat16* Bhi = reinterpret_cast<__nv_bfloat16*>(smem + SM_BHI);
    __nv_bfloat16* Blo = reinterpret_cast<__nv_bfloat16*>(smem + SM_BLO);
    float* stage = reinterpret_cast<float*>(smem);   // [64][132] aliased

    const int tid = threadIdx.x;
    const int w  = tid >> 5;
    const int wm = w >> 2;              // 0..1 : 64-row group
    const int wn = w & 3;               // 0..3 : 32-col group
    const int rowBase = blockIdx.x * 128;

    // A-load: 2 threads per row; each handles 16 consecutive k (4 float4)
    const int ar = tid >> 1;            // 0..127
    const int akc = (tid & 1) * 16;     // 0 or 16
    const int agrow = rowBase + ar;
    const bool aval = agrow < NN;
    // B-load: 16 threads per k-row, 8 bf16 each
    const int kr = tid >> 4;            // 0..15
    const int nc = (tid & 15) * 8;      // 0..120

    wmma::fragment<wmma::accumulator, 16, 16, 16, float> acc[4][2];
    #pragma unroll
    for (int i = 0; i < 4; i++)
        #pragma unroll
        for (int j = 0; j < 2; j++) wmma::fill_fragment(acc[i][j], 0.f);

    for (int kb = 0; kb < 8; kb++) {
        // ---- A tile: 128 rows x 32 k, f32 load + split to bf16 hi/lo ----
        const float* A = (kb < 4) ? g_mean : h;
        int k0 = (kb & 3) * 32 + akc;
        #pragma unroll
        for (int q = 0; q < 4; q++) {
            float4 v = make_float4(0.f, 0.f, 0.f, 0.f);
            if (aval)
                v = *reinterpret_cast<const float4*>(A + (size_t)agrow * DD + k0 + q * 4);
            split4(v,
                   reinterpret_cast<uint2*>(Ahi + ar * ALD + akc + q * 4),
                   reinterpret_cast<uint2*>(Alo + ar * ALD + akc + q * 4));
        }
        // ---- B tile: 32 k x 128 n (pre-split bf16) ----
        #pragma unroll
        for (int half = 0; half < 2; half++) {
            int krow = kr + half * 16;
            size_t go = (size_t)lw + (size_t)(kb * 32 + krow) * DD + nc;
            *reinterpret_cast<uint4*>(Bhi + krow * BLD + nc) =
                *reinterpret_cast<const uint4*>(g_Whi + go);
            *reinterpret_cast<uint4*>(Blo + krow * BLD + nc) =
                *reinterpret_cast<const uint4*>(g_Wlo + go);
        }
        __syncthreads();

        #pragma unroll
        for (int kk = 0; kk < 32; kk += 16) {
            wmma::fragment<wmma::matrix_b, 16, 16, 16, __nv_bfloat16, wmma::row_major> bh[2], blo[2];
            #pragma unroll
            for (int j = 0; j < 2; j++) {
                wmma::load_matrix_sync(bh[j],  Bhi + kk * BLD + wn * 32 + j * 16, BLD);
                wmma::load_matrix_sync(blo[j], Blo + kk * BLD + wn * 32 + j * 16, BLD);
            }
            #pragma unroll
            for (int i = 0; i < 4; i++) {
                wmma::fragment<wmma::matrix_a, 16, 16, 16, __nv_bfloat16, wmma::row_major> ah, al;
                wmma::load_matrix_sync(ah, Ahi + (wm * 64 + i * 16) * ALD + kk, ALD);
                wmma::load_matrix_sync(al, Alo + (wm * 64 + i * 16) * ALD + kk, ALD);
                #pragma unroll
                for (int j = 0; j < 2; j++) {
                    wmma::mma_sync(acc[i][j], ah, bh[j],  acc[i][j]);
                    wmma::mma_sync(acc[i][j], ah, blo[j], acc[i][j]);
                    wmma::mma_sync(acc[i][j], al, bh[j],  acc[i][j]);
                }
            }
        }
        __syncthreads();
    }

    // ---- epilogue in two 64-row halves (stage aliases the tile smem) ----
    #pragma unroll
    for (int ph = 0; ph < 2; ph++) {
        if (wm == ph) {
            #pragma unroll
            for (int i = 0; i < 4; i++)
                #pragma unroll
                for (int j = 0; j < 2; j++)
                    wmma::store_matrix_sync(stage + (i * 16) * STG_LD + wn * 32 + j * 16,
                                            acc[i][j], STG_LD, wmma::mem_row_major);
        }
        __syncthreads();
        #pragma unroll
        for (int it = 0; it < 8; it++) {
            int idx = it * 256 + tid;          // 0..2047
            int row = idx >> 5;                // 0..63
            int c4  = (idx & 31) * 4;          // 0..124
            int grow = rowBase + ph * 64 + row;
            if (grow < NN) {
                const float* sp = stage + row * STG_LD + c4;
                float4 bb = *reinterpret_cast<const float4*>(bias + c4);
                float4 hv = *reinterpret_cast<const float4*>(h + (size_t)grow * DD + c4);
                float4 o;
                o.x = sp[0] + bb.x + hv.x;
                o.y = sp[1] + bb.y + hv.y;
                o.z = sp[2] + bb.z + hv.z;
                o.w = sp[3] + bb.w + hv.w;
                if (do_relu) {
                    o.x = fmaxf(o.x, 0.f); o.y = fmaxf(o.y, 0.f);
                    o.z = fmaxf(o.z, 0.f); o.w = fmaxf(o.w, 0.f);
                }
                *reinterpret_cast<float4*>(out + (size_t)grow * DD + c4) = o;
            }
        }
        __syncthreads();
    }
}

// ---------------- launch ----------------
extern "C" void kernel_launch(void* const* d_in, const int* in_sizes, int n_in,
                              void* d_out, int out_size) {
    const float* x  = (const float*)d_in[0];
    const int*   ei = (const int*)d_in[1];
    const float* Wl = (const float*)d_in[2];
    const float* bl = (const float*)d_in[3];
    const float* Wr = (const float*)d_in[4];
    const int* src = ei;
    const int* dst = ei + NE;
    float* out = (float*)d_out;

    const int SB = 1184;
    const int GATHERB = (NN * 32 + 255) / 256;   // one warp per node
    const int GB = (NN + 127) / 128;             // 782 gemm blocks

    // CSR build (graph fixed across layers)
    zero_cnt_kernel<<<(NN + 255) / 256, 256>>>();
    hist_kernel<<<SB, 256>>>(dst);
    scan_kernel<<<1, 1024>>>();
    fill_kernel<<<SB, 256>>>(src, dst);

    // weight split
    convert_w_kernel<<<(3 * KK * DD + 255) / 256, 256>>>(Wl, Wr);

    // layer 0: x -> g_buf0 (relu)
    gather_kernel<<<GATHERB, 256>>>(x, 0);
    sage_wmma_kernel<<<GB, 256>>>(x, out, bl, 0 * KK * DD, 0, 0, 1);

    // layer 1: g_buf0 -> g_buf1 (relu)
    gather_kernel<<<GATHERB, 256>>>(x, 1);
    sage_wmma_kernel<<<GB, 256>>>(x, out, bl + DD, 1 * KK * DD, 1, 1, 1);

    // layer 2: g_buf1 -> out (no relu)
    gather_kernel<<<GATHERB, 256>>>(x, 2);
    sage_wmma_kernel<<<GB, 256>>>(x, out, bl + 2 * DD, 2 * KK * DD, 2, 2, 0);
}